// round 16
// baseline (speedup 1.0000x reference)
#include <cuda_runtime.h>
#include <cuda_fp16.h>

typedef unsigned int u32;
typedef unsigned short u16;

#define T_LEN 512
#define D_IN  5
#define NB    32
#define GRID  128
#define NTHR  512          // 16 warps; warp w owns M-tile w

// ---- smem byte offsets ----
#define OFF_A0  0          // L0 A frags (fp16): 16 tiles x 4 kb x 512B = 32768
#define OFF_A1  32768      // L1 A frags: 16 x 8 x 512B = 65536
#define OFF_B0H 98304      // h0 hi  [32][72] fp16 = 4608
#define OFF_B0L 102912     // h0 lo
#define OFF_B1H 107520     // [h1|h0] hi [32][136] fp16 = 8704
#define OFF_B1L 116224     // [h1|h0] lo
#define OFF_XS  124928     // x stage [5][32] f32 = 640
#define SMEM_BYTES 125568

#define PK0 72             // B0 pitch (fp16 elems)
#define PK1 136            // B1 pitch

__device__ __forceinline__ u16 hfbits(float v) {
    __half h = __float2half_rn(v);
    return reinterpret_cast<__half_raw&>(h).x;
}
__device__ __forceinline__ float hff(u16 b) {
    __half_raw r; r.x = b;
    return __half2float(*reinterpret_cast<__half*>(&r));
}
__device__ __forceinline__ u32 pack_h2(float v0, float v1) {
    return (u32)hfbits(v0) | ((u32)hfbits(v1) << 16);
}

__device__ __forceinline__ u32 smem_u32(const void* p) {
    u32 a;
    asm("{ .reg .u64 t; cvta.to.shared.u64 t, %1; cvt.u32.u64 %0, t; }" : "=r"(a) : "l"(p));
    return a;
}
__device__ __forceinline__ void lds128(u32* v, u32 addr) {
    asm volatile("ld.shared.v4.u32 {%0,%1,%2,%3}, [%4];"
        : "=r"(v[0]), "=r"(v[1]), "=r"(v[2]), "=r"(v[3]) : "r"(addr));
}
__device__ __forceinline__ void mma16816(float* d, const u32* a, u32 b0, u32 b1) {
    asm volatile("mma.sync.aligned.m16n8k16.row.col.f32.f16.f16.f32 "
        "{%0,%1,%2,%3}, {%4,%5,%6,%7}, {%8,%9}, {%0,%1,%2,%3};"
        : "+f"(d[0]), "+f"(d[1]), "+f"(d[2]), "+f"(d[3])
        : "r"(a[0]), "r"(a[1]), "r"(a[2]), "r"(a[3]), "r"(b0), "r"(b1));
}

// MUFU.TANH (validated across all passing rounds)
__device__ __forceinline__ float tanha(float x) {
    float y; asm("tanh.approx.f32 %0, %1;" : "=f"(y) : "f"(x)); return y;
}
__device__ __forceinline__ float sigf(float x) {
    return fmaf(0.5f, tanha(0.5f * x), 0.5f);
}

// A-frag byte offsets (frag-contiguous: [tile][kb][lane][4xu32])
__device__ __forceinline__ u32 a0_off(int tile, int kb, int lane) {
    return OFF_A0 + (u32)(((tile * 4 + kb) * 32 + lane) * 16);
}
__device__ __forceinline__ u32 a1_off(int tile, int kb, int lane) {
    return OFF_A1 + (u32)(((tile * 8 + kb) * 32 + lane) * 16);
}

__global__ void __launch_bounds__(NTHR, 1)
stocklstm_mma_kernel(const float* __restrict__ x,
                     const float* __restrict__ W_ih0, const float* __restrict__ W_hh0,
                     const float* __restrict__ b_ih0, const float* __restrict__ b_hh0,
                     const float* __restrict__ W_ih1, const float* __restrict__ W_hh1,
                     const float* __restrict__ b_ih1, const float* __restrict__ b_hh1,
                     const float* __restrict__ W1,   const float* __restrict__ b1,
                     const float* __restrict__ W2,   const float* __restrict__ b2,
                     float* __restrict__ out)
{
    extern __shared__ char sm[];
    const u32 sb = smem_u32(sm);
    const int tid  = threadIdx.x;
    const int w    = tid >> 5;       // warp = M-tile 0..15
    const int lane = tid & 31;
    const int grp  = lane >> 2;      // 0..7
    const int tig  = lane & 3;       // 0..3
    const int par  = grp >> 2;       // 0: lane holds (i,g); 1: (f,o)
    const int B0   = blockIdx.x * NB;

    // ---- stage A0 frags (Whh0 fp16, gate-interleaved rows) ----
    for (int idx = tid; idx < 8192; idx += NTHR) {
        int reg = idx & 3, ln = (idx >> 2) & 31, kb = (idx >> 7) & 3;
        int tile = idx >> 9;
        int g2 = ln >> 2, t2 = ln & 3;
        int row = g2 + (reg & 1) * 8;
        int col = kb * 16 + t2 * 2 + (reg >> 1) * 8;
        int grow = ((row >> 2) << 6) + tile * 4 + (row & 3);  // gate*64 + unit
        ((u32*)(sm + OFF_A0))[idx] =
            pack_h2(W_hh0[grow * 64 + col], W_hh0[grow * 64 + col + 1]);
    }
    // ---- stage A1 frags ([Whh1 | Wih1] along K=128) ----
    for (int idx = tid; idx < 16384; idx += NTHR) {
        int reg = idx & 3, ln = (idx >> 2) & 31, kb = (idx >> 7) & 7;
        int tile = idx >> 10;
        int g2 = ln >> 2, t2 = ln & 3;
        int row = g2 + (reg & 1) * 8;
        int col = kb * 16 + t2 * 2 + (reg >> 1) * 8;  // 0..127
        int grow = ((row >> 2) << 6) + tile * 4 + (row & 3);
        float v0, v1;
        if (col < 64) { v0 = W_hh1[grow * 64 + col];      v1 = W_hh1[grow * 64 + col + 1]; }
        else          { v0 = W_ih1[grow * 64 + col - 64]; v1 = W_ih1[grow * 64 + col - 63]; }
        ((u32*)(sm + OFF_A1))[idx] = pack_h2(v0, v1);
    }
    // ---- zero B buffers ----
    for (int idx = tid; idx < 6656; idx += NTHR)
        ((u32*)(sm + OFF_B0H))[idx] = 0u;

    // ---- per-thread constants (single tile) ----
    const int ga = par;               // gate_a: 0(i) or 1(f)
    const int gc = ga + 2;            // gate_c: 2(g) or 3(o)
    const int uu = 4 * w + (grp & 3); // hidden unit 0..63

    const int ra = ga * 64 + uu, rc = gc * 64 + uu;
    const float bA0 = b_ih0[ra] + b_hh0[ra];
    const float bC0 = b_ih0[rc] + b_hh0[rc];
    const float bA1 = b_ih1[ra] + b_hh1[ra];
    const float bC1 = b_ih1[rc] + b_hh1[rc];
    float wxA[5], wxC[5];
#pragma unroll
    for (int d = 0; d < 5; d++) {
        wxA[d] = W_ih0[ra * 5 + d];
        wxC[d] = W_ih0[rc * 5 + d];
    }

    float c0[4], c1[4], hfin[4];
#pragma unroll
    for (int p = 0; p < 4; p++) { c0[p] = 0.0f; c1[p] = 0.0f; hfin[p] = 0.0f; }

    // ---- x staging: threads 0..159 own (batch xl, feature xd) ----
    const int xl = tid / 5, xd = tid - xl * 5;
    const float* xptr = x + (size_t)(B0 + xl) * (T_LEN * D_IN) + xd;
    float xreg = 0.0f;
    if (tid < 160) {
        ((float*)(sm + OFF_XS))[xd * 32 + xl] = xptr[0];
        xreg = xptr[D_IN];
    }
    __syncthreads();

#pragma unroll 1
    for (int t = 0; t < T_LEN; t++) {
        float d[4][4];
        // ===== L0 D-init: bias + Wih0 @ x (fp32 scalar) =====
#pragma unroll
        for (int nb = 0; nb < 4; nb++) {
            float s0 = bA0, s1 = bA0, s2 = bC0, s3 = bC0;
#pragma unroll
            for (int dd = 0; dd < 5; dd++) {
                float2 xv = *(const float2*)((const float*)(sm + OFF_XS) + dd * 32 + nb * 8 + tig * 2);
                s0 = fmaf(wxA[dd], xv.x, s0); s1 = fmaf(wxA[dd], xv.y, s1);
                s2 = fmaf(wxC[dd], xv.x, s2); s3 = fmaf(wxC[dd], xv.y, s3);
            }
            d[nb][0] = s0; d[nb][1] = s1; d[nb][2] = s2; d[nb][3] = s3;
        }
        // ===== L0 mma: Whh0_f16 @ (h0_hi + h0_lo) =====
#pragma unroll
        for (int kb = 0; kb < 4; kb++) {
            u32 a0[4];
            lds128(a0, sb + a0_off(w, kb, lane));
#pragma unroll
            for (int nb = 0; nb < 4; nb++) {
                u32 bo = (u32)((nb * 8 + grp) * (PK0 * 2) + (kb * 16 + tig * 2) * 2);
                u32 bh0 = *(const u32*)(sm + OFF_B0H + bo);
                u32 bh1 = *(const u32*)(sm + OFF_B0H + bo + 16);
                u32 bl0 = *(const u32*)(sm + OFF_B0L + bo);
                u32 bl1 = *(const u32*)(sm + OFF_B0L + bo + 16);
                mma16816(d[nb], a0, bh0, bh1);
                mma16816(d[nb], a0, bl0, bl1);
            }
        }
        __syncthreads();   // S1: all L0 B-reads (h0 old) + x reads done

        // stage x[t+1]; prefetch x[t+2]
        if (tid < 160) {
            ((float*)(sm + OFF_XS))[xd * 32 + xl] = xreg;
            int tn = (t + 2 < T_LEN) ? t + 2 : T_LEN - 1;
            xreg = xptr[tn * D_IN];
        }

        // ===== pointwise L0 (warp-local via shfl) =====
#pragma unroll
        for (int nb = 0; nb < 4; nb++) {
            float d0 = d[nb][0], d1 = d[nb][1], d2 = d[nb][2], d3 = d[nb][3];
            float p0 = __shfl_xor_sync(0xFFFFFFFFu, d0, 16);
            float p1 = __shfl_xor_sync(0xFFFFFFFFu, d1, 16);
            float p2 = __shfl_xor_sync(0xFFFFFFFFu, d2, 16);
            float p3 = __shfl_xor_sync(0xFFFFFFFFu, d3, 16);
            float vi = par ? p1 : d0;
            float vf = par ? d1 : p0;
            float vg = par ? p3 : d2;
            float vo = par ? d3 : p2;
            float cc = sigf(vf) * c0[nb] + sigf(vi) * tanha(vg);
            c0[nb] = cc;
            float h = sigf(vo) * tanha(cc);
            u16 hb = hfbits(h);
            u16 lb = hfbits(h - hff(hb));
            int b = nb * 8 + tig * 2 + par;
            ((u16*)(sm + OFF_B0H))[b * PK0 + uu] = hb;        // next step's L0
            ((u16*)(sm + OFF_B0L))[b * PK0 + uu] = lb;
            ((u16*)(sm + OFF_B1H))[b * PK1 + 64 + uu] = hb;   // this step's L1 (Wih1 half)
            ((u16*)(sm + OFF_B1L))[b * PK1 + 64 + uu] = lb;
        }
        __syncthreads();   // S2: h0 new visible

        // ===== L1 D-init (bias) + mma: [Whh1|Wih1]_f16 @ ([h1;h0]_hi + lo) =====
#pragma unroll
        for (int nb = 0; nb < 4; nb++) {
            d[nb][0] = bA1; d[nb][1] = bA1;
            d[nb][2] = bC1; d[nb][3] = bC1;
        }
#pragma unroll
        for (int kb = 0; kb < 8; kb++) {
            u32 a0[4];
            lds128(a0, sb + a1_off(w, kb, lane));
#pragma unroll
            for (int nb = 0; nb < 4; nb++) {
                u32 bo = (u32)((nb * 8 + grp) * (PK1 * 2) + (kb * 16 + tig * 2) * 2);
                u32 bh0 = *(const u32*)(sm + OFF_B1H + bo);
                u32 bh1 = *(const u32*)(sm + OFF_B1H + bo + 16);
                u32 bl0 = *(const u32*)(sm + OFF_B1L + bo);
                u32 bl1 = *(const u32*)(sm + OFF_B1L + bo + 16);
                mma16816(d[nb], a0, bh0, bh1);
                mma16816(d[nb], a0, bl0, bl1);
            }
        }
        __syncthreads();   // S3: all L1 B-reads done (h1 WAR safe)

        // ===== pointwise L1 =====
#pragma unroll
        for (int nb = 0; nb < 4; nb++) {
            float d0 = d[nb][0], d1 = d[nb][1], d2 = d[nb][2], d3 = d[nb][3];
            float p0 = __shfl_xor_sync(0xFFFFFFFFu, d0, 16);
            float p1 = __shfl_xor_sync(0xFFFFFFFFu, d1, 16);
            float p2 = __shfl_xor_sync(0xFFFFFFFFu, d2, 16);
            float p3 = __shfl_xor_sync(0xFFFFFFFFu, d3, 16);
            float vi = par ? p1 : d0;
            float vf = par ? d1 : p0;
            float vg = par ? p3 : d2;
            float vo = par ? d3 : p2;
            float cc = sigf(vf) * c1[nb] + sigf(vi) * tanha(vg);
            c1[nb] = cc;
            float h = sigf(vo) * tanha(cc);
            hfin[nb] = h;
            u16 hb = hfbits(h);
            u16 lb = hfbits(h - hff(hb));
            int b = nb * 8 + tig * 2 + par;
            ((u16*)(sm + OFF_B1H))[b * PK1 + uu] = hb;   // h1 (Whh1 half)
            ((u16*)(sm + OFF_B1L))[b * PK1 + uu] = lb;
        }
        // h1-new visibility for next step's L1 covered by next iter's S2
    }

    // ---- stash final h1 (fp32) for the MLP head (reuse B0 region: 9216B >= 8448) ----
    {
        float* scr = (float*)(sm + OFF_B0H);   // [64][33] f32
#pragma unroll
        for (int nb = 0; nb < 4; nb++) {
            int b = nb * 8 + tig * 2 + par;
            scr[uu * 33 + b] = hfin[nb];
        }
    }
    __syncthreads();

    // ---- MLP head: out = W2 @ relu(W1 @ h2 + b1) + b2 ----
    if (tid < NB) {
        const float* scr = (const float*)(sm + OFF_B0H);
        float acc = b2[0];
#pragma unroll 1
        for (int u = 0; u < 32; u++) {
            float s = b1[u];
            const float* wr = W1 + u * 64;
#pragma unroll
            for (int k = 0; k < 64; k++) s += wr[k] * scr[k * 33 + tid];
            acc += W2[u] * fmaxf(s, 0.0f);
        }
        out[B0 + tid] = acc;
    }
}

extern "C" void kernel_launch(void* const* d_in, const int* in_sizes, int n_in,
                              void* d_out, int out_size)
{
    const float* x    = (const float*)d_in[0];
    const float* Wih0 = (const float*)d_in[1];
    const float* Whh0 = (const float*)d_in[2];
    const float* bih0 = (const float*)d_in[3];
    const float* bhh0 = (const float*)d_in[4];
    const float* Wih1 = (const float*)d_in[5];
    const float* Whh1 = (const float*)d_in[6];
    const float* bih1 = (const float*)d_in[7];
    const float* bhh1 = (const float*)d_in[8];
    const float* W1   = (const float*)d_in[9];
    const float* b1   = (const float*)d_in[10];
    const float* W2   = (const float*)d_in[11];
    const float* b2   = (const float*)d_in[12];
    float* out = (float*)d_out;

    cudaFuncSetAttribute(stocklstm_mma_kernel,
                         cudaFuncAttributeMaxDynamicSharedMemorySize, SMEM_BYTES);
    stocklstm_mma_kernel<<<GRID, NTHR, SMEM_BYTES>>>(
        x, Wih0, Whh0, bih0, bhh0, Wih1, Whh1, bih1, bhh1, W1, b1, W2, b2, out);
}

// round 17
// speedup vs baseline: 1.2092x; 1.2092x over previous
#include <cuda_runtime.h>
#include <cuda_fp16.h>

typedef unsigned int u32;
typedef unsigned short u16;

#define T_LEN 512
#define D_IN  5
#define NB    32
#define GRID  128
#define NTHR  256          // 8 warps; warp w owns M-tiles {2w, 2w+1}

// ---- smem byte offsets ----
#define OFF_A0  0          // L0 A frags (fp16): 16 tiles x 4 kb x 512B = 32768 (staging only)
#define OFF_A1  32768      // L1 A frags: 16 x 8 x 512B = 65536 (staging only)
#define OFF_B0H 98304      // h0 hi  [32][72] fp16 = 4608
#define OFF_B0L 102912     // h0 lo
#define OFF_B1H 107520     // [h1|h0] hi [32][136] fp16 = 8704
#define OFF_B1L 116224     // [h1|h0] lo
#define OFF_XS  124928     // x stage [5][32] f32 = 640
#define SMEM_BYTES 125568

#define PK0 72             // B0 pitch (fp16 elems)
#define PK1 136            // B1 pitch

__device__ __forceinline__ u16 hfbits(float v) {
    __half h = __float2half_rn(v);
    return reinterpret_cast<__half_raw&>(h).x;
}
__device__ __forceinline__ float hff(u16 b) {
    __half_raw r; r.x = b;
    return __half2float(*reinterpret_cast<__half*>(&r));
}
__device__ __forceinline__ u32 pack_h2(float v0, float v1) {
    return (u32)hfbits(v0) | ((u32)hfbits(v1) << 16);
}

__device__ __forceinline__ u32 smem_u32(const void* p) {
    u32 a;
    asm("{ .reg .u64 t; cvta.to.shared.u64 t, %1; cvt.u32.u64 %0, t; }" : "=r"(a) : "l"(p));
    return a;
}
__device__ __forceinline__ void lds128(u32* v, u32 addr) {
    asm volatile("ld.shared.v4.u32 {%0,%1,%2,%3}, [%4];"
        : "=r"(v[0]), "=r"(v[1]), "=r"(v[2]), "=r"(v[3]) : "r"(addr));
}
__device__ __forceinline__ void mma16816(float* d, const u32* a, u32 b0, u32 b1) {
    asm volatile("mma.sync.aligned.m16n8k16.row.col.f32.f16.f16.f32 "
        "{%0,%1,%2,%3}, {%4,%5,%6,%7}, {%8,%9}, {%0,%1,%2,%3};"
        : "+f"(d[0]), "+f"(d[1]), "+f"(d[2]), "+f"(d[3])
        : "r"(a[0]), "r"(a[1]), "r"(a[2]), "r"(a[3]), "r"(b0), "r"(b1));
}

// MUFU.TANH (validated across all passing rounds)
__device__ __forceinline__ float tanha(float x) {
    float y; asm("tanh.approx.f32 %0, %1;" : "=f"(y) : "f"(x)); return y;
}
__device__ __forceinline__ float sigf(float x) {
    return fmaf(0.5f, tanha(0.5f * x), 0.5f);
}

// A-frag byte offsets (staging layout: [tile][kb][lane][4xu32])
__device__ __forceinline__ u32 a0_off(int tile, int kb, int lane) {
    return OFF_A0 + (u32)(((tile * 4 + kb) * 32 + lane) * 16);
}
__device__ __forceinline__ u32 a1_off(int tile, int kb, int lane) {
    return OFF_A1 + (u32)(((tile * 8 + kb) * 32 + lane) * 16);
}

__global__ void __launch_bounds__(NTHR, 1)
stocklstm_mma_kernel(const float* __restrict__ x,
                     const float* __restrict__ W_ih0, const float* __restrict__ W_hh0,
                     const float* __restrict__ b_ih0, const float* __restrict__ b_hh0,
                     const float* __restrict__ W_ih1, const float* __restrict__ W_hh1,
                     const float* __restrict__ b_ih1, const float* __restrict__ b_hh1,
                     const float* __restrict__ W1,   const float* __restrict__ b1,
                     const float* __restrict__ W2,   const float* __restrict__ b2,
                     float* __restrict__ out)
{
    extern __shared__ char sm[];
    const u32 sb = smem_u32(sm);
    const int tid  = threadIdx.x;
    const int w    = tid >> 5;
    const int lane = tid & 31;
    const int grp  = lane >> 2;      // 0..7
    const int tig  = lane & 3;       // 0..3
    const int par  = grp >> 2;       // 0: lane holds (i,g); 1: (f,o)
    const int B0   = blockIdx.x * NB;

    // ---- stage A0 frags (Whh0 fp16, gate-interleaved rows) into smem ----
    for (int idx = tid; idx < 8192; idx += NTHR) {
        int reg = idx & 3, ln = (idx >> 2) & 31, kb = (idx >> 7) & 3;
        int tile = idx >> 9;
        int g2 = ln >> 2, t2 = ln & 3;
        int row = g2 + (reg & 1) * 8;
        int col = kb * 16 + t2 * 2 + (reg >> 1) * 8;
        int grow = ((row >> 2) << 6) + tile * 4 + (row & 3);  // gate*64 + unit
        ((u32*)(sm + OFF_A0))[idx] =
            pack_h2(W_hh0[grow * 64 + col], W_hh0[grow * 64 + col + 1]);
    }
    // ---- stage A1 frags ([Whh1 | Wih1] along K=128) ----
    for (int idx = tid; idx < 16384; idx += NTHR) {
        int reg = idx & 3, ln = (idx >> 2) & 31, kb = (idx >> 7) & 7;
        int tile = idx >> 10;
        int g2 = ln >> 2, t2 = ln & 3;
        int row = g2 + (reg & 1) * 8;
        int col = kb * 16 + t2 * 2 + (reg >> 1) * 8;  // 0..127
        int grow = ((row >> 2) << 6) + tile * 4 + (row & 3);
        float v0, v1;
        if (col < 64) { v0 = W_hh1[grow * 64 + col];      v1 = W_hh1[grow * 64 + col + 1]; }
        else          { v0 = W_ih1[grow * 64 + col - 64]; v1 = W_ih1[grow * 64 + col - 63]; }
        ((u32*)(sm + OFF_A1))[idx] = pack_h2(v0, v1);
    }
    // ---- zero B buffers (h0 = h1 = 0) ----
    for (int idx = tid; idx < 6656; idx += NTHR)
        ((u32*)(sm + OFF_B0H))[idx] = 0u;

    // ---- per-thread constants ----
    const int tg[2] = { 2 * w, 2 * w + 1 };
    const int ga = grp >> 2;          // gate_a: 0(i) or 1(f)
    const int gc = ga + 2;            // gate_c: 2(g) or 3(o)
    const int uu[2] = { 4 * tg[0] + (grp & 3), 4 * tg[1] + (grp & 3) };

    float bA0[2], bC0[2], bA1[2], bC1[2];
    float wxA[2][5], wxC[2][5];
#pragma unroll
    for (int t2 = 0; t2 < 2; t2++) {
        int ra = ga * 64 + uu[t2], rc = gc * 64 + uu[t2];
        bA0[t2] = b_ih0[ra] + b_hh0[ra];
        bC0[t2] = b_ih0[rc] + b_hh0[rc];
        bA1[t2] = b_ih1[ra] + b_hh1[ra];
        bC1[t2] = b_ih1[rc] + b_hh1[rc];
#pragma unroll
        for (int d = 0; d < 5; d++) {
            wxA[t2][d] = W_ih0[ra * 5 + d];
            wxC[t2][d] = W_ih0[rc * 5 + d];
        }
    }

    float c0[8], c1[8], hfin[8];
#pragma unroll
    for (int p = 0; p < 8; p++) { c0[p] = 0.0f; c1[p] = 0.0f; hfin[p] = 0.0f; }

    // ---- x staging: threads 0..159 own (batch xl, feature xd) ----
    const int xl = tid / 5, xd = tid - xl * 5;
    const float* xptr = x + (size_t)(B0 + xl) * (T_LEN * D_IN) + xd;
    float xreg = 0.0f;
    if (tid < 160) {
        ((float*)(sm + OFF_XS))[xd * 32 + xl] = xptr[0];
        xreg = xptr[D_IN];
    }
    __syncthreads();

    // ---- hoist ALL A fragments into registers (loop-invariant weights) ----
    u32 A0r[2][4][4];   // [tile][kb][reg]
    u32 A1r[2][8][4];
#pragma unroll
    for (int t2 = 0; t2 < 2; t2++) {
#pragma unroll
        for (int kb = 0; kb < 4; kb++) lds128(A0r[t2][kb], sb + a0_off(tg[t2], kb, lane));
#pragma unroll
        for (int kb = 0; kb < 8; kb++) lds128(A1r[t2][kb], sb + a1_off(tg[t2], kb, lane));
    }

#pragma unroll 1
    for (int t = 0; t < T_LEN; t++) {
        float d[2][4][4];
        // ===== L0 D-init: bias + Wih0 @ x (fp32 scalar) =====
#pragma unroll
        for (int t2 = 0; t2 < 2; t2++)
#pragma unroll
            for (int nb = 0; nb < 4; nb++) {
                float s0 = bA0[t2], s1 = bA0[t2], s2 = bC0[t2], s3 = bC0[t2];
#pragma unroll
                for (int dd = 0; dd < 5; dd++) {
                    float2 xv = *(const float2*)((const float*)(sm + OFF_XS) + dd * 32 + nb * 8 + tig * 2);
                    s0 = fmaf(wxA[t2][dd], xv.x, s0); s1 = fmaf(wxA[t2][dd], xv.y, s1);
                    s2 = fmaf(wxC[t2][dd], xv.x, s2); s3 = fmaf(wxC[t2][dd], xv.y, s3);
                }
                d[t2][nb][0] = s0; d[t2][nb][1] = s1; d[t2][nb][2] = s2; d[t2][nb][3] = s3;
            }
        // ===== L0 mma: Whh0_f16 @ (h0_hi + h0_lo), A in registers =====
#pragma unroll
        for (int kb = 0; kb < 4; kb++) {
#pragma unroll
            for (int nb = 0; nb < 4; nb++) {
                u32 bo = (u32)((nb * 8 + grp) * (PK0 * 2) + (kb * 16 + tig * 2) * 2);
                u32 bh0 = *(const u32*)(sm + OFF_B0H + bo);
                u32 bh1 = *(const u32*)(sm + OFF_B0H + bo + 16);
                u32 bl0 = *(const u32*)(sm + OFF_B0L + bo);
                u32 bl1 = *(const u32*)(sm + OFF_B0L + bo + 16);
                mma16816(d[0][nb], A0r[0][kb], bh0, bh1);
                mma16816(d[0][nb], A0r[0][kb], bl0, bl1);
                mma16816(d[1][nb], A0r[1][kb], bh0, bh1);
                mma16816(d[1][nb], A0r[1][kb], bl0, bl1);
            }
        }
        __syncthreads();   // S1: all L0 B-reads (h0 old) + x reads done

        // stage x[t+1]; prefetch x[t+2]
        if (tid < 160) {
            ((float*)(sm + OFF_XS))[xd * 32 + xl] = xreg;
            int tn = (t + 2 < T_LEN) ? t + 2 : T_LEN - 1;
            xreg = xptr[tn * D_IN];
        }

        // ===== pointwise L0 (warp-local via shfl) =====
#pragma unroll
        for (int t2 = 0; t2 < 2; t2++)
#pragma unroll
            for (int nb = 0; nb < 4; nb++) {
                float d0 = d[t2][nb][0], d1 = d[t2][nb][1], d2 = d[t2][nb][2], d3 = d[t2][nb][3];
                float p0 = __shfl_xor_sync(0xFFFFFFFFu, d0, 16);
                float p1 = __shfl_xor_sync(0xFFFFFFFFu, d1, 16);
                float p2 = __shfl_xor_sync(0xFFFFFFFFu, d2, 16);
                float p3 = __shfl_xor_sync(0xFFFFFFFFu, d3, 16);
                float vi = par ? p1 : d0;
                float vf = par ? d1 : p0;
                float vg = par ? p3 : d2;
                float vo = par ? d3 : p2;
                float cc = sigf(vf) * c0[t2 * 4 + nb] + sigf(vi) * tanha(vg);
                c0[t2 * 4 + nb] = cc;
                float h = sigf(vo) * tanha(cc);
                u16 hb = hfbits(h);
                u16 lb = hfbits(h - hff(hb));
                int b = nb * 8 + tig * 2 + par;
                int u = uu[t2];
                ((u16*)(sm + OFF_B0H))[b * PK0 + u] = hb;        // next step's L0
                ((u16*)(sm + OFF_B0L))[b * PK0 + u] = lb;
                ((u16*)(sm + OFF_B1H))[b * PK1 + 64 + u] = hb;   // this step's L1 (Wih1 half)
                ((u16*)(sm + OFF_B1L))[b * PK1 + 64 + u] = lb;
            }
        __syncthreads();   // S2: h0 new visible

        // ===== L1 D-init (bias) + mma: [Whh1|Wih1]_f16 @ ([h1;h0]_hi + lo) =====
#pragma unroll
        for (int t2 = 0; t2 < 2; t2++)
#pragma unroll
            for (int nb = 0; nb < 4; nb++) {
                d[t2][nb][0] = bA1[t2]; d[t2][nb][1] = bA1[t2];
                d[t2][nb][2] = bC1[t2]; d[t2][nb][3] = bC1[t2];
            }
#pragma unroll
        for (int kb = 0; kb < 8; kb++) {
#pragma unroll
            for (int nb = 0; nb < 4; nb++) {
                u32 bo = (u32)((nb * 8 + grp) * (PK1 * 2) + (kb * 16 + tig * 2) * 2);
                u32 bh0 = *(const u32*)(sm + OFF_B1H + bo);
                u32 bh1 = *(const u32*)(sm + OFF_B1H + bo + 16);
                u32 bl0 = *(const u32*)(sm + OFF_B1L + bo);
                u32 bl1 = *(const u32*)(sm + OFF_B1L + bo + 16);
                mma16816(d[0][nb], A1r[0][kb], bh0, bh1);
                mma16816(d[0][nb], A1r[0][kb], bl0, bl1);
                mma16816(d[1][nb], A1r[1][kb], bh0, bh1);
                mma16816(d[1][nb], A1r[1][kb], bl0, bl1);
            }
        }
        __syncthreads();   // S3: all L1 B-reads done (h1 WAR safe)

        // ===== pointwise L1 =====
#pragma unroll
        for (int t2 = 0; t2 < 2; t2++)
#pragma unroll
            for (int nb = 0; nb < 4; nb++) {
                float d0 = d[t2][nb][0], d1 = d[t2][nb][1], d2 = d[t2][nb][2], d3 = d[t2][nb][3];
                float p0 = __shfl_xor_sync(0xFFFFFFFFu, d0, 16);
                float p1 = __shfl_xor_sync(0xFFFFFFFFu, d1, 16);
                float p2 = __shfl_xor_sync(0xFFFFFFFFu, d2, 16);
                float p3 = __shfl_xor_sync(0xFFFFFFFFu, d3, 16);
                float vi = par ? p1 : d0;
                float vf = par ? d1 : p0;
                float vg = par ? p3 : d2;
                float vo = par ? d3 : p2;
                float cc = sigf(vf) * c1[t2 * 4 + nb] + sigf(vi) * tanha(vg);
                c1[t2 * 4 + nb] = cc;
                float h = sigf(vo) * tanha(cc);
                hfin[t2 * 4 + nb] = h;
                u16 hb = hfbits(h);
                u16 lb = hfbits(h - hff(hb));
                int b = nb * 8 + tig * 2 + par;
                int u = uu[t2];
                ((u16*)(sm + OFF_B1H))[b * PK1 + u] = hb;   // h1 (Whh1 half)
                ((u16*)(sm + OFF_B1L))[b * PK1 + u] = lb;
            }
        // h1-new visibility for next step's L1 covered by next iter's S2
    }

    // ---- stash final h1 (fp32) for the MLP head (reuse B0 region: 9216B >= 8448) ----
    {
        float* scr = (float*)(sm + OFF_B0H);   // [64][33] f32
#pragma unroll
        for (int t2 = 0; t2 < 2; t2++)
#pragma unroll
            for (int nb = 0; nb < 4; nb++) {
                int b = nb * 8 + tig * 2 + par;
                scr[uu[t2] * 33 + b] = hfin[t2 * 4 + nb];
            }
    }
    __syncthreads();

    // ---- MLP head: out = W2 @ relu(W1 @ h2 + b1) + b2 ----
    if (tid < NB) {
        const float* scr = (const float*)(sm + OFF_B0H);
        float acc = b2[0];
#pragma unroll 1
        for (int u = 0; u < 32; u++) {
            float s = b1[u];
            const float* wr = W1 + u * 64;
#pragma unroll
            for (int k = 0; k < 64; k++) s += wr[k] * scr[k * 33 + tid];
            acc += W2[u] * fmaxf(s, 0.0f);
        }
        out[B0 + tid] = acc;
    }
}

extern "C" void kernel_launch(void* const* d_in, const int* in_sizes, int n_in,
                              void* d_out, int out_size)
{
    const float* x    = (const float*)d_in[0];
    const float* Wih0 = (const float*)d_in[1];
    const float* Whh0 = (const float*)d_in[2];
    const float* bih0 = (const float*)d_in[3];
    const float* bhh0 = (const float*)d_in[4];
    const float* Wih1 = (const float*)d_in[5];
    const float* Whh1 = (const float*)d_in[6];
    const float* bih1 = (const float*)d_in[7];
    const float* bhh1 = (const float*)d_in[8];
    const float* W1   = (const float*)d_in[9];
    const float* b1   = (const float*)d_in[10];
    const float* W2   = (const float*)d_in[11];
    const float* b2   = (const float*)d_in[12];
    float* out = (float*)d_out;

    cudaFuncSetAttribute(stocklstm_mma_kernel,
                         cudaFuncAttributeMaxDynamicSharedMemorySize, SMEM_BYTES);
    stocklstm_mma_kernel<<<GRID, NTHR, SMEM_BYTES>>>(
        x, Wih0, Whh0, bih0, bhh0, Wih1, Whh1, bih1, bhh1, W1, b1, W2, b2, out);
}